// round 1
// baseline (speedup 1.0000x reference)
#include <cuda_runtime.h>
#include <cstdint>

#define HDIM 128
#define NMAX 500000
#define PNUM 50000
#define LN_EPS 1e-5f

// ---------------- scratch (static __device__; no allocation) ----------------
__device__ float g_h0[(size_t)NMAX * HDIM];   // h0, later reused as h2
__device__ float g_h1[(size_t)NMAX * HDIM];
__device__ float g_agg[(size_t)PNUM * HDIM];
__device__ int   g_counts[PNUM];
__device__ int   g_offsets[PNUM + 1];
__device__ int   g_cursor[PNUM];
__device__ int   g_order[NMAX];
__device__ int   g_ids[NMAX];
__device__ int   g_ids64;

// ---------------- id dtype detection + normalization ----------------
__global__ void detect_ids_kernel(const void* idsraw) {
    // If the buffer is really int64 (little-endian, values in [0,P)), the first
    // 16 int64 words are all in-range. If it is int32 data, interpreting pairs
    // as int64 yields huge values unless every odd id is 0 (prob ~0).
    const long long* a = (const long long*)idsraw;
    int ok = 1;
    for (int i = 0; i < 16; i++) {
        long long v = a[i];
        if (v < 0 || v >= PNUM) ok = 0;
    }
    g_ids64 = ok;
}

__global__ void convert_ids_kernel(const void* idsraw, int N) {
    int i = blockIdx.x * blockDim.x + threadIdx.x;
    if (i >= N) return;
    int v = g_ids64 ? (int)((const long long*)idsraw)[i]
                    : ((const int*)idsraw)[i];
    g_ids[i] = v;
}

// ---------------- CSR build ----------------
__global__ void zero_counts_kernel() {
    int i = blockIdx.x * blockDim.x + threadIdx.x;
    if (i < PNUM) g_counts[i] = 0;
}

__global__ void hist_kernel(int N) {
    int i = blockIdx.x * blockDim.x + threadIdx.x;
    if (i < N) atomicAdd(&g_counts[g_ids[i]], 1);
}

__global__ void scan_kernel() {
    __shared__ int sums[1024];
    int t = threadIdx.x;
    const int per = (PNUM + 1023) / 1024;           // 49
    int start = t * per;
    int end = start + per; if (end > PNUM) end = PNUM;
    int s = 0;
    for (int i = start; i < end; i++) s += g_counts[i];
    sums[t] = s;
    __syncthreads();
    // Hillis–Steele inclusive scan
    for (int off = 1; off < 1024; off <<= 1) {
        int v = (t >= off) ? sums[t - off] : 0;
        __syncthreads();
        sums[t] += v;
        __syncthreads();
    }
    int run = (t == 0) ? 0 : sums[t - 1];
    for (int i = start; i < end; i++) {
        g_offsets[i] = run;
        g_cursor[i] = run;
        run += g_counts[i];
    }
    if (t == 1023) g_offsets[PNUM] = run;
}

__global__ void scatter_kernel(int N) {
    int i = blockIdx.x * blockDim.x + threadIdx.x;
    if (i >= N) return;
    int pos = atomicAdd(&g_cursor[g_ids[i]], 1);
    g_order[pos] = i;   // order within segment nondeterministic; max is commutative
}

// ---------------- encoder 0: [N,9] @ [9,128] + LN + ReLU ----------------
__global__ __launch_bounds__(256) void enc0_kernel(
    const float* __restrict__ x, const float* __restrict__ W0,
    const float* __restrict__ b0, const float* __restrict__ g0,
    const float* __restrict__ be0, float* __restrict__ out, int N)
{
    int warp = (blockIdx.x * blockDim.x + threadIdx.x) >> 5;
    int lane = threadIdx.x & 31;
    if (warp >= N) return;

    float xv = (lane < 9) ? x[(size_t)warp * 9 + lane] : 0.f;
    float z[4];
#pragma unroll
    for (int c = 0; c < 4; c++) z[c] = b0[lane + 32 * c];
#pragma unroll
    for (int k = 0; k < 9; k++) {
        float xk = __shfl_sync(0xffffffffu, xv, k);
#pragma unroll
        for (int c = 0; c < 4; c++)
            z[c] = fmaf(xk, W0[k * HDIM + lane + 32 * c], z[c]);
    }
    float s  = z[0] + z[1] + z[2] + z[3];
    float s2 = z[0]*z[0] + z[1]*z[1] + z[2]*z[2] + z[3]*z[3];
#pragma unroll
    for (int o = 16; o > 0; o >>= 1) {
        s  += __shfl_xor_sync(0xffffffffu, s, o);
        s2 += __shfl_xor_sync(0xffffffffu, s2, o);
    }
    float mu  = s * (1.f / HDIM);
    float var = fmaf(s2, 1.f / HDIM, -mu * mu);
    float rs  = rsqrtf(var + LN_EPS);
#pragma unroll
    for (int c = 0; c < 4; c++) {
        int j = lane + 32 * c;
        float v = fmaf((z[c] - mu) * rs, g0[j], be0[j]);
        out[(size_t)warp * HDIM + j] = fmaxf(v, 0.f);
    }
}

// ---------------- segmented max: warp per polyline ----------------
__global__ __launch_bounds__(256) void segmax_kernel(
    const float* __restrict__ h, float* __restrict__ out, int P)
{
    int p    = (blockIdx.x * blockDim.x + threadIdx.x) >> 5;
    int lane = threadIdx.x & 31;
    if (p >= P) return;
    int beg = g_offsets[p], end = g_offsets[p + 1];
    float4 m = make_float4(0.f, 0.f, 0.f, 0.f);   // ReLU outputs >= 0; empty -> 0
    for (int i = beg; i < end; i++) {
        int row = g_order[i];
        float4 v = *(const float4*)(h + (size_t)row * HDIM + lane * 4);
        m.x = fmaxf(m.x, v.x); m.y = fmaxf(m.y, v.y);
        m.z = fmaxf(m.z, v.z); m.w = fmaxf(m.w, v.w);
    }
    *(float4*)(out + (size_t)p * HDIM + lane * 4) = m;
}

// ---------------- encoder 1/2: [N,256] @ [256,128] + LN + ReLU ----------------
// concat([h_prev, agg[ids]]) done implicitly while staging A.
// BM=32 rows/block, BK=32, 128 threads, thread tile 8x4.
__global__ __launch_bounds__(128) void enc_kernel(
    const float* __restrict__ hprev, const float* __restrict__ agg,
    const float* __restrict__ W, const float* __restrict__ b,
    const float* __restrict__ gw, const float* __restrict__ be,
    float* __restrict__ out, int N)
{
    __shared__ __align__(16) float As[32][36];   // [k][m], padded
    __shared__ __align__(16) float Ws[32][HDIM]; // [k][n]
    __shared__ int rid[32];

    int tid = threadIdx.x;
    int tx = tid & 31;          // column group: cols tx*4 .. tx*4+3
    int ty = tid >> 5;          // warp id: rows ty*8 .. ty*8+7
    int row0 = blockIdx.x * 32;

    if (tid < 32) {
        int r = row0 + tid;
        rid[tid] = g_ids[(r < N) ? r : 0];
    }

    float acc[8][4];
#pragma unroll
    for (int r = 0; r < 8; r++)
#pragma unroll
        for (int c = 0; c < 4; c++) acc[r][c] = 0.f;

#pragma unroll 1
    for (int kc = 0; kc < 8; kc++) {
        __syncthreads();
        int kb = kc * 32;
        // A chunk: 32 rows x 32 k (transposed into As[k][m])
#pragma unroll
        for (int i = 0; i < 2; i++) {
            int idx = tid + i * 128;        // 0..255
            int r = idx >> 3;               // row 0..31
            int f = idx & 7;                // float4 idx -> k = f*4
            int gr = row0 + r; if (gr >= N) gr = row0;
            const float* p = (kc < 4)
                ? (hprev + (size_t)gr * HDIM + kb + f * 4)
                : (agg + (size_t)rid[r] * HDIM + (kb - HDIM) + f * 4);
            float4 v = *(const float4*)p;
            As[f*4+0][r] = v.x; As[f*4+1][r] = v.y;
            As[f*4+2][r] = v.z; As[f*4+3][r] = v.w;
        }
        // W chunk: 32 x 128
#pragma unroll
        for (int i = 0; i < 8; i++) {
            int idx = tid + i * 128;        // float4 index 0..1023
            int k = idx >> 5, f = idx & 31;
            *(float4*)&Ws[k][f * 4] =
                *(const float4*)(W + (size_t)(kb + k) * HDIM + f * 4);
        }
        __syncthreads();
#pragma unroll
        for (int k = 0; k < 32; k++) {
            float4 wv = *(const float4*)&Ws[k][tx * 4];
            float4 a0 = *(const float4*)&As[k][ty * 8];
            float4 a1 = *(const float4*)&As[k][ty * 8 + 4];
            float a[8] = {a0.x, a0.y, a0.z, a0.w, a1.x, a1.y, a1.z, a1.w};
            float w[4] = {wv.x, wv.y, wv.z, wv.w};
#pragma unroll
            for (int r = 0; r < 8; r++)
#pragma unroll
                for (int c = 0; c < 4; c++)
                    acc[r][c] = fmaf(a[r], w[c], acc[r][c]);
        }
    }

    // Epilogue: warp ty owns rows ty*8..ty*8+7 across all 128 cols -> warp-shuffle LN.
    float4 bv = *(const float4*)&b[tx * 4];
    float4 gv = *(const float4*)&gw[tx * 4];
    float4 ev = *(const float4*)&be[tx * 4];
#pragma unroll
    for (int r = 0; r < 8; r++) {
        float z0 = acc[r][0] + bv.x, z1 = acc[r][1] + bv.y;
        float z2 = acc[r][2] + bv.z, z3 = acc[r][3] + bv.w;
        float s  = z0 + z1 + z2 + z3;
        float s2 = z0*z0 + z1*z1 + z2*z2 + z3*z3;
#pragma unroll
        for (int o = 16; o > 0; o >>= 1) {
            s  += __shfl_xor_sync(0xffffffffu, s, o);
            s2 += __shfl_xor_sync(0xffffffffu, s2, o);
        }
        float mu  = s * (1.f / HDIM);
        float var = fmaf(s2, 1.f / HDIM, -mu * mu);
        float rs  = rsqrtf(var + LN_EPS);
        float4 o4;
        o4.x = fmaxf(fmaf((z0 - mu) * rs, gv.x, ev.x), 0.f);
        o4.y = fmaxf(fmaf((z1 - mu) * rs, gv.y, ev.y), 0.f);
        o4.z = fmaxf(fmaf((z2 - mu) * rs, gv.z, ev.z), 0.f);
        o4.w = fmaxf(fmaf((z3 - mu) * rs, gv.w, ev.w), 0.f);
        int grow = row0 + ty * 8 + r;
        if (grow < N)
            *(float4*)(out + (size_t)grow * HDIM + tx * 4) = o4;
    }
}

// ---------------- output tail (unique_polylines = arange(P)) ----------------
__global__ void tail_kernel(float* out, int tail) {
    int i = blockIdx.x * blockDim.x + threadIdx.x;
    float* base = out + (size_t)PNUM * HDIM;
    if (tail == PNUM) {
        if (i < PNUM) base[i] = (float)i;
    } else if (tail == 2 * PNUM) {
        if (i < PNUM) ((long long*)base)[i] = (long long)i;
    } else {
        if (i < tail) base[i] = (float)i;
    }
}

// ---------------- launch ----------------
extern "C" void kernel_launch(void* const* d_in, const int* in_sizes, int n_in,
                              void* d_out, int out_size) {
    const float* x   = (const float*)d_in[0];
    const void*  ids = d_in[1];
    const float* W0  = (const float*)d_in[2];
    const float* b0  = (const float*)d_in[3];
    const float* g0  = (const float*)d_in[4];
    const float* be0 = (const float*)d_in[5];
    const float* W1  = (const float*)d_in[6];
    const float* b1  = (const float*)d_in[7];
    const float* g1  = (const float*)d_in[8];
    const float* be1 = (const float*)d_in[9];
    const float* W2  = (const float*)d_in[10];
    const float* b2  = (const float*)d_in[11];
    const float* g2  = (const float*)d_in[12];
    const float* be2 = (const float*)d_in[13];

    const int N = in_sizes[0] / 9;          // 500000
    const int P = PNUM;                     // 50000 (fixed by problem)
    float* out = (float*)d_out;

    float *h0, *h1, *agg;
    cudaGetSymbolAddress((void**)&h0,  g_h0);
    cudaGetSymbolAddress((void**)&h1,  g_h1);
    cudaGetSymbolAddress((void**)&agg, g_agg);

    // 1) id normalization + CSR build
    detect_ids_kernel<<<1, 1>>>(ids);
    convert_ids_kernel<<<(N + 255) / 256, 256>>>(ids, N);
    zero_counts_kernel<<<(P + 255) / 256, 256>>>();
    hist_kernel<<<(N + 255) / 256, 256>>>(N);
    scan_kernel<<<1, 1024>>>();
    scatter_kernel<<<(N + 255) / 256, 256>>>(N);

    // 2) enc0 -> h0
    enc0_kernel<<<(N + 7) / 8, 256>>>(x, W0, b0, g0, be0, h0, N);

    // 3) seg_max(h0) -> agg ; enc1 -> h1
    segmax_kernel<<<(P + 7) / 8, 256>>>(h0, agg, P);
    enc_kernel<<<(N + 31) / 32, 128>>>(h0, agg, W1, b1, g1, be1, h1, N);

    // 4) seg_max(h1) -> agg ; enc2 -> h0 (reused as h2)
    segmax_kernel<<<(P + 7) / 8, 256>>>(h1, agg, P);
    enc_kernel<<<(N + 31) / 32, 128>>>(h1, agg, W2, b2, g2, be2, h0, N);

    // 5) final seg_max(h2) -> d_out features; arange tail if present
    segmax_kernel<<<(P + 7) / 8, 256>>>(h0, out, P);
    int tail = out_size - P * HDIM;
    if (tail > 0) {
        int elems = (tail == 2 * PNUM) ? PNUM : tail;
        tail_kernel<<<(elems + 255) / 256, 256>>>(out, tail);
    }
}

// round 2
// speedup vs baseline: 2.1579x; 2.1579x over previous
#include <cuda_runtime.h>
#include <cstdint>

#define HDIM 128
#define NMAX 500000
#define PNUM 50000
#define LN_EPS 1e-5f

// ---------------- scratch (static __device__; no allocation) ----------------
__device__ float g_h0[(size_t)NMAX * HDIM];   // h0, later reused as h2
__device__ float g_h1[(size_t)NMAX * HDIM];
__device__ float g_agg[(size_t)PNUM * HDIM];
__device__ int   g_counts[PNUM];
__device__ int   g_offsets[PNUM + 1];
__device__ int   g_cursor[PNUM];
__device__ int   g_order[NMAX];
__device__ int   g_ids[NMAX];
__device__ int   g_ids64;

// ---------------- id dtype detection + normalization ----------------
__global__ void detect_ids_kernel(const void* idsraw) {
    const long long* a = (const long long*)idsraw;
    int ok = 1;
    for (int i = 0; i < 16; i++) {
        long long v = a[i];
        if (v < 0 || v >= PNUM) ok = 0;
    }
    g_ids64 = ok;
}

__global__ void convert_ids_kernel(const void* idsraw, int N) {
    int i = blockIdx.x * blockDim.x + threadIdx.x;
    if (i >= N) return;
    int v = g_ids64 ? (int)((const long long*)idsraw)[i]
                    : ((const int*)idsraw)[i];
    g_ids[i] = v;
}

// ---------------- CSR build ----------------
__global__ void zero_counts_kernel() {
    int i = blockIdx.x * blockDim.x + threadIdx.x;
    if (i < PNUM) g_counts[i] = 0;
}

__global__ void hist_kernel(int N) {
    int i = blockIdx.x * blockDim.x + threadIdx.x;
    if (i < N) atomicAdd(&g_counts[g_ids[i]], 1);
}

__global__ void scan_kernel() {
    __shared__ int sums[1024];
    int t = threadIdx.x;
    const int per = (PNUM + 1023) / 1024;
    int start = t * per;
    int end = start + per; if (end > PNUM) end = PNUM;
    int s = 0;
    for (int i = start; i < end; i++) s += g_counts[i];
    sums[t] = s;
    __syncthreads();
    for (int off = 1; off < 1024; off <<= 1) {
        int v = (t >= off) ? sums[t - off] : 0;
        __syncthreads();
        sums[t] += v;
        __syncthreads();
    }
    int run = (t == 0) ? 0 : sums[t - 1];
    for (int i = start; i < end; i++) {
        g_offsets[i] = run;
        g_cursor[i] = run;
        run += g_counts[i];
    }
    if (t == 1023) g_offsets[PNUM] = run;
}

__global__ void scatter_kernel(int N) {
    int i = blockIdx.x * blockDim.x + threadIdx.x;
    if (i >= N) return;
    int pos = atomicAdd(&g_cursor[g_ids[i]], 1);
    g_order[pos] = i;
}

// ---------------- encoder 0: [N,9] @ [9,128] + LN + ReLU ----------------
__global__ __launch_bounds__(256) void enc0_kernel(
    const float* __restrict__ x, const float* __restrict__ W0,
    const float* __restrict__ b0, const float* __restrict__ g0,
    const float* __restrict__ be0, float* __restrict__ out, int N)
{
    int warp = (blockIdx.x * blockDim.x + threadIdx.x) >> 5;
    int lane = threadIdx.x & 31;
    if (warp >= N) return;

    float xv = (lane < 9) ? x[(size_t)warp * 9 + lane] : 0.f;
    float z[4];
#pragma unroll
    for (int c = 0; c < 4; c++) z[c] = b0[lane + 32 * c];
#pragma unroll
    for (int k = 0; k < 9; k++) {
        float xk = __shfl_sync(0xffffffffu, xv, k);
#pragma unroll
        for (int c = 0; c < 4; c++)
            z[c] = fmaf(xk, W0[k * HDIM + lane + 32 * c], z[c]);
    }
    float s  = z[0] + z[1] + z[2] + z[3];
    float s2 = z[0]*z[0] + z[1]*z[1] + z[2]*z[2] + z[3]*z[3];
#pragma unroll
    for (int o = 16; o > 0; o >>= 1) {
        s  += __shfl_xor_sync(0xffffffffu, s, o);
        s2 += __shfl_xor_sync(0xffffffffu, s2, o);
    }
    float mu  = s * (1.f / HDIM);
    float var = fmaf(s2, 1.f / HDIM, -mu * mu);
    float rs  = rsqrtf(var + LN_EPS);
#pragma unroll
    for (int c = 0; c < 4; c++) {
        int j = lane + 32 * c;
        float v = fmaf((z[c] - mu) * rs, g0[j], be0[j]);
        out[(size_t)warp * HDIM + j] = fmaxf(v, 0.f);
    }
}

// ---------------- segmented max: warp per polyline ----------------
__global__ __launch_bounds__(256) void segmax_kernel(
    const float* __restrict__ h, float* __restrict__ out, int P)
{
    int p    = (blockIdx.x * blockDim.x + threadIdx.x) >> 5;
    int lane = threadIdx.x & 31;
    if (p >= P) return;
    int beg = g_offsets[p], end = g_offsets[p + 1];
    float4 m = make_float4(0.f, 0.f, 0.f, 0.f);
    for (int i = beg; i < end; i++) {
        int row = g_order[i];
        float4 v = *(const float4*)(h + (size_t)row * HDIM + lane * 4);
        m.x = fmaxf(m.x, v.x); m.y = fmaxf(m.y, v.y);
        m.z = fmaxf(m.z, v.z); m.w = fmaxf(m.w, v.w);
    }
    *(float4*)(out + (size_t)p * HDIM + lane * 4) = m;
}

// ---------------- tf32 mma.sync helpers ----------------
__device__ __forceinline__ void cp_async16(float* s, const float* g) {
    unsigned sa = (unsigned)__cvta_generic_to_shared(s);
    asm volatile("cp.async.cg.shared.global [%0], [%1], 16;\n" :: "r"(sa), "l"(g));
}
__device__ __forceinline__ void cp_commit() {
    asm volatile("cp.async.commit_group;\n" ::: "memory");
}
template<int n> __device__ __forceinline__ void cp_wait() {
    asm volatile("cp.async.wait_group %0;\n" :: "n"(n) : "memory");
}
__device__ __forceinline__ void mma_tf32(float acc[4], const unsigned a[4], const unsigned b[2]) {
    asm volatile(
        "mma.sync.aligned.m16n8k8.row.col.f32.tf32.tf32.f32 "
        "{%0,%1,%2,%3},{%4,%5,%6,%7},{%8,%9},{%0,%1,%2,%3};\n"
        : "+f"(acc[0]), "+f"(acc[1]), "+f"(acc[2]), "+f"(acc[3])
        : "r"(a[0]), "r"(a[1]), "r"(a[2]), "r"(a[3]), "r"(b[0]), "r"(b[1]));
}

// ---------------- encoder 1/2 (tensor-core tf32) ----------------
// CTA: 128 rows x 128 cols x K=256.  8 warps as 4(M) x 2(N); warp tile 32x64.
// A smem [m][k] stride 36 (bank-free a-frags); W smem [k][n] stride 136.
// Double-buffered BK=32 chunks via cp.async. Fused LN+ReLU epilogue.
#define AS_STRIDE 36
#define WS_STRIDE 136
#define AS_BUF (128 * AS_STRIDE)       // 4608 floats
#define WS_BUF (32 * WS_STRIDE)        // 4352 floats
#define ENC_SMEM_FLOATS (2*AS_BUF + 2*WS_BUF + 512 + 128)
#define ENC_SMEM_BYTES (ENC_SMEM_FLOATS * 4)

__global__ __launch_bounds__(256, 2) void enc_kernel(
    const float* __restrict__ hprev, const float* __restrict__ agg,
    const float* __restrict__ W, const float* __restrict__ b,
    const float* __restrict__ gw, const float* __restrict__ be,
    float* __restrict__ out, int N)
{
    extern __shared__ float sm[];
    float* As   = sm;                           // [2][128][36]
    float* Wsm  = sm + 2 * AS_BUF;              // [2][32][136]
    float2* red2 = (float2*)(sm + 2*AS_BUF + 2*WS_BUF);   // [128][2]
    int*   ridp = (int*)(sm + 2*AS_BUF + 2*WS_BUF + 512); // [128]

    const int tid = threadIdx.x;
    const int lane = tid & 31;
    const int quad_r = lane >> 2, quad_c = lane & 3;
    const int warp = tid >> 5;
    const int warp_m = warp >> 1, warp_n = warp & 1;
    const int row0 = blockIdx.x * 128;

    if (tid < 128) {
        int r = row0 + tid;
        ridp[tid] = g_ids[(r < N) ? r : (N - 1)];
    }
    __syncthreads();

    float acc[2][8][4];
#pragma unroll
    for (int mf = 0; mf < 2; mf++)
#pragma unroll
        for (int nt = 0; nt < 8; nt++)
#pragma unroll
            for (int c = 0; c < 4; c++) acc[mf][nt][c] = 0.f;

    // ---- async stager for chunk kc into buffer buf ----
    auto issue_chunk = [&](int kc, int buf) {
        float* Ab = As + buf * AS_BUF;
        float* Wb = Wsm + buf * WS_BUF;
#pragma unroll
        for (int i = 0; i < 4; i++) {
            int idx = tid + i * 256;        // 0..1023
            int r = idx >> 3, f = idx & 7;
            const float* src;
            if (kc < 4) {
                int gr = row0 + r; if (gr >= N) gr = N - 1;
                src = hprev + (size_t)gr * HDIM + kc * 32 + f * 4;
            } else {
                src = agg + (size_t)ridp[r] * HDIM + (kc - 4) * 32 + f * 4;
            }
            cp_async16(Ab + r * AS_STRIDE + f * 4, src);
        }
#pragma unroll
        for (int i = 0; i < 4; i++) {
            int idx = tid + i * 256;
            int k = idx >> 5, f = idx & 31;
            cp_async16(Wb + k * WS_STRIDE + f * 4,
                       W + (size_t)(kc * 32 + k) * HDIM + f * 4);
        }
        cp_commit();
    };

    issue_chunk(0, 0);

#pragma unroll 1
    for (int kc = 0; kc < 8; kc++) {
        if (kc < 7) { issue_chunk(kc + 1, (kc + 1) & 1); cp_wait<1>(); }
        else        { cp_wait<0>(); }
        __syncthreads();

        const float* Ab = As + (kc & 1) * AS_BUF;
        const float* Wb = Wsm + (kc & 1) * WS_BUF;
#pragma unroll
        for (int ks = 0; ks < 4; ks++) {
            const int kk = ks * 8;
            unsigned afr[2][4];
#pragma unroll
            for (int mf = 0; mf < 2; mf++) {
                const float* p = Ab + (warp_m * 32 + mf * 16 + quad_r) * AS_STRIDE
                                    + kk + quad_c;
                afr[mf][0] = __float_as_uint(p[0]);
                afr[mf][1] = __float_as_uint(p[8 * AS_STRIDE]);
                afr[mf][2] = __float_as_uint(p[4]);
                afr[mf][3] = __float_as_uint(p[8 * AS_STRIDE + 4]);
            }
            unsigned bfr[8][2];
#pragma unroll
            for (int nt = 0; nt < 8; nt++) {
                const float* p = Wb + (kk + quad_c) * WS_STRIDE
                                    + warp_n * 64 + nt * 8 + quad_r;
                bfr[nt][0] = __float_as_uint(p[0]);
                bfr[nt][1] = __float_as_uint(p[4 * WS_STRIDE]);
            }
#pragma unroll
            for (int mf = 0; mf < 2; mf++)
#pragma unroll
                for (int nt = 0; nt < 8; nt++)
                    mma_tf32(acc[mf][nt], afr[mf], bfr[nt]);
        }
        __syncthreads();
    }

    // ---- epilogue: bias + LayerNorm + ReLU ----
    // add bias
#pragma unroll
    for (int nt = 0; nt < 8; nt++) {
        float2 bv = *(const float2*)&b[warp_n * 64 + nt * 8 + quad_c * 2];
#pragma unroll
        for (int mf = 0; mf < 2; mf++) {
            acc[mf][nt][0] += bv.x; acc[mf][nt][1] += bv.y;
            acc[mf][nt][2] += bv.x; acc[mf][nt][3] += bv.y;
        }
    }
    // per-row partial sums over this warp's 64 cols
    float s[2][2], q[2][2];
#pragma unroll
    for (int mf = 0; mf < 2; mf++)
#pragma unroll
        for (int h = 0; h < 2; h++) {
            float ss = 0.f, qq = 0.f;
#pragma unroll
            for (int nt = 0; nt < 8; nt++) {
                float z0 = acc[mf][nt][2 * h], z1 = acc[mf][nt][2 * h + 1];
                ss += z0 + z1;
                qq += z0 * z0 + z1 * z1;
            }
            s[mf][h] = ss; q[mf][h] = qq;
        }
#pragma unroll
    for (int mk = 1; mk <= 2; mk <<= 1)
#pragma unroll
        for (int mf = 0; mf < 2; mf++)
#pragma unroll
            for (int h = 0; h < 2; h++) {
                s[mf][h] += __shfl_xor_sync(0xffffffffu, s[mf][h], mk);
                q[mf][h] += __shfl_xor_sync(0xffffffffu, q[mf][h], mk);
            }
    if (quad_c == 0) {
#pragma unroll
        for (int mf = 0; mf < 2; mf++)
#pragma unroll
            for (int h = 0; h < 2; h++) {
                int rl = warp_m * 32 + mf * 16 + h * 8 + quad_r;
                red2[rl * 2 + warp_n] = make_float2(s[mf][h], q[mf][h]);
            }
    }
    __syncthreads();
    float mu[2][2], rs[2][2];
#pragma unroll
    for (int mf = 0; mf < 2; mf++)
#pragma unroll
        for (int h = 0; h < 2; h++) {
            int rl = warp_m * 32 + mf * 16 + h * 8 + quad_r;
            float2 r0 = red2[rl * 2 + 0], r1 = red2[rl * 2 + 1];
            float ss = r0.x + r1.x, qq = r0.y + r1.y;
            float m = ss * (1.f / HDIM);
            float var = fmaf(qq, 1.f / HDIM, -m * m);
            mu[mf][h] = m;
            rs[mf][h] = rsqrtf(var + LN_EPS);
        }
#pragma unroll
    for (int nt = 0; nt < 8; nt++) {
        int col = warp_n * 64 + nt * 8 + quad_c * 2;
        float2 gv = *(const float2*)&gw[col];
        float2 ev = *(const float2*)&be[col];
#pragma unroll
        for (int mf = 0; mf < 2; mf++)
#pragma unroll
            for (int h = 0; h < 2; h++) {
                int grow = row0 + warp_m * 32 + mf * 16 + h * 8 + quad_r;
                if (grow < N) {
                    float z0 = acc[mf][nt][2 * h], z1 = acc[mf][nt][2 * h + 1];
                    float2 o;
                    o.x = fmaxf(fmaf((z0 - mu[mf][h]) * rs[mf][h], gv.x, ev.x), 0.f);
                    o.y = fmaxf(fmaf((z1 - mu[mf][h]) * rs[mf][h], gv.y, ev.y), 0.f);
                    *(float2*)(out + (size_t)grow * HDIM + col) = o;
                }
            }
    }
}

// ---------------- output tail (unique_polylines = arange(P)) ----------------
__global__ void tail_kernel(float* out, int tail) {
    int i = blockIdx.x * blockDim.x + threadIdx.x;
    float* base = out + (size_t)PNUM * HDIM;
    if (tail == PNUM) {
        if (i < PNUM) base[i] = (float)i;
    } else if (tail == 2 * PNUM) {
        if (i < PNUM) ((long long*)base)[i] = (long long)i;
    } else {
        if (i < tail) base[i] = (float)i;
    }
}

// ---------------- launch ----------------
extern "C" void kernel_launch(void* const* d_in, const int* in_sizes, int n_in,
                              void* d_out, int out_size) {
    const float* x   = (const float*)d_in[0];
    const void*  ids = d_in[1];
    const float* W0  = (const float*)d_in[2];
    const float* b0  = (const float*)d_in[3];
    const float* g0  = (const float*)d_in[4];
    const float* be0 = (const float*)d_in[5];
    const float* W1  = (const float*)d_in[6];
    const float* b1  = (const float*)d_in[7];
    const float* g1  = (const float*)d_in[8];
    const float* be1 = (const float*)d_in[9];
    const float* W2  = (const float*)d_in[10];
    const float* b2  = (const float*)d_in[11];
    const float* g2  = (const float*)d_in[12];
    const float* be2 = (const float*)d_in[13];

    const int N = in_sizes[0] / 9;
    const int P = PNUM;
    float* out = (float*)d_out;

    float *h0, *h1, *agg;
    cudaGetSymbolAddress((void**)&h0,  g_h0);
    cudaGetSymbolAddress((void**)&h1,  g_h1);
    cudaGetSymbolAddress((void**)&agg, g_agg);

    cudaFuncSetAttribute(enc_kernel,
        cudaFuncAttributeMaxDynamicSharedMemorySize, ENC_SMEM_BYTES);

    // 1) id normalization + CSR build
    detect_ids_kernel<<<1, 1>>>(ids);
    convert_ids_kernel<<<(N + 255) / 256, 256>>>(ids, N);
    zero_counts_kernel<<<(P + 255) / 256, 256>>>();
    hist_kernel<<<(N + 255) / 256, 256>>>(N);
    scan_kernel<<<1, 1024>>>();
    scatter_kernel<<<(N + 255) / 256, 256>>>(N);

    // 2) enc0 -> h0
    enc0_kernel<<<(N + 7) / 8, 256>>>(x, W0, b0, g0, be0, h0, N);

    // 3) seg_max(h0) -> agg ; enc1 -> h1
    segmax_kernel<<<(P + 7) / 8, 256>>>(h0, agg, P);
    enc_kernel<<<(N + 127) / 128, 256, ENC_SMEM_BYTES>>>(h0, agg, W1, b1, g1, be1, h1, N);

    // 4) seg_max(h1) -> agg ; enc2 -> h0
    segmax_kernel<<<(P + 7) / 8, 256>>>(h1, agg, P);
    enc_kernel<<<(N + 127) / 128, 256, ENC_SMEM_BYTES>>>(h1, agg, W2, b2, g2, be2, h0, N);

    // 5) final seg_max(h2) -> d_out features; arange tail if present
    segmax_kernel<<<(P + 7) / 8, 256>>>(h0, out, P);
    int tail = out_size - P * HDIM;
    if (tail > 0) {
        int elems = (tail == 2 * PNUM) ? PNUM : tail;
        tail_kernel<<<(elems + 255) / 256, 256>>>(out, tail);
    }
}

// round 3
// speedup vs baseline: 2.5956x; 1.2028x over previous
#include <cuda_runtime.h>
#include <cstdint>

#define HDIM 128
#define NMAX 500000
#define PNUM 50000
#define LN_EPS 1e-5f

// ---------------- scratch (static __device__; no allocation) ----------------
__device__ float g_h0[(size_t)NMAX * HDIM];   // h0, later reused as h2
__device__ float g_h1[(size_t)NMAX * HDIM];
__device__ float g_agg[(size_t)PNUM * HDIM];
__device__ float g_aggw[(size_t)PNUM * HDIM];
__device__ int   g_counts[PNUM];
__device__ int   g_offsets[PNUM + 1];
__device__ int   g_cursor[PNUM];
__device__ int   g_order[NMAX];   // sorted position -> original row
__device__ int   g_ids[NMAX];     // original row -> id
__device__ int   g_sid[NMAX];     // sorted position -> id (non-decreasing)
__device__ int   g_ids64;

// ---------------- id dtype detection ----------------
__global__ void detect_ids_kernel(const void* idsraw) {
    const long long* a = (const long long*)idsraw;
    int ok = 1;
    for (int i = 0; i < 16; i++) {
        long long v = a[i];
        if (v < 0 || v >= PNUM) ok = 0;
    }
    g_ids64 = ok;
}

// convert ids + histogram in one pass (counts pre-zeroed via memset)
__global__ void prep_kernel(const void* idsraw, int N) {
    int i = blockIdx.x * blockDim.x + threadIdx.x;
    if (i >= N) return;
    int v = g_ids64 ? (int)((const long long*)idsraw)[i]
                    : ((const int*)idsraw)[i];
    g_ids[i] = v;
    atomicAdd(&g_counts[v], 1);
}

__global__ void scan_kernel() {
    __shared__ int sums[1024];
    int t = threadIdx.x;
    const int per = (PNUM + 1023) / 1024;
    int start = t * per;
    int end = start + per; if (end > PNUM) end = PNUM;
    int s = 0;
    for (int i = start; i < end; i++) s += g_counts[i];
    sums[t] = s;
    __syncthreads();
    for (int off = 1; off < 1024; off <<= 1) {
        int v = (t >= off) ? sums[t - off] : 0;
        __syncthreads();
        sums[t] += v;
        __syncthreads();
    }
    int run = (t == 0) ? 0 : sums[t - 1];
    for (int i = start; i < end; i++) {
        g_offsets[i] = run;
        g_cursor[i] = run;
        run += g_counts[i];
    }
    if (t == 1023) g_offsets[PNUM] = run;
}

__global__ void scatter_kernel(int N) {
    int i = blockIdx.x * blockDim.x + threadIdx.x;
    if (i >= N) return;
    int id = g_ids[i];
    int pos = atomicAdd(&g_cursor[id], 1);
    g_order[pos] = i;
    g_sid[pos] = id;
}

// ---------------- encoder 0 (sorted output space) ----------------
__global__ __launch_bounds__(256) void enc0_kernel(
    const float* __restrict__ x, const float* __restrict__ W0,
    const float* __restrict__ b0, const float* __restrict__ g0,
    const float* __restrict__ be0, float* __restrict__ out, int N)
{
    int spos = (blockIdx.x * blockDim.x + threadIdx.x) >> 5;  // sorted index
    int lane = threadIdx.x & 31;
    if (spos >= N) return;
    int srow = g_order[spos];

    float xv = (lane < 9) ? x[(size_t)srow * 9 + lane] : 0.f;
    float z[4];
#pragma unroll
    for (int c = 0; c < 4; c++) z[c] = b0[lane + 32 * c];
#pragma unroll
    for (int k = 0; k < 9; k++) {
        float xk = __shfl_sync(0xffffffffu, xv, k);
#pragma unroll
        for (int c = 0; c < 4; c++)
            z[c] = fmaf(xk, W0[k * HDIM + lane + 32 * c], z[c]);
    }
    float s  = z[0] + z[1] + z[2] + z[3];
    float s2 = z[0]*z[0] + z[1]*z[1] + z[2]*z[2] + z[3]*z[3];
#pragma unroll
    for (int o = 16; o > 0; o >>= 1) {
        s  += __shfl_xor_sync(0xffffffffu, s, o);
        s2 += __shfl_xor_sync(0xffffffffu, s2, o);
    }
    float mu  = s * (1.f / HDIM);
    float var = fmaf(s2, 1.f / HDIM, -mu * mu);
    float rs  = rsqrtf(var + LN_EPS);
#pragma unroll
    for (int c = 0; c < 4; c++) {
        int j = lane + 32 * c;
        float v = fmaf((z[c] - mu) * rs, g0[j], be0[j]);
        out[(size_t)spos * HDIM + j] = fmaxf(v, 0.f);
    }
}

// ---------------- segmented max: warp per polyline, contiguous rows ----------
__global__ __launch_bounds__(256) void segmax_kernel(
    const float* __restrict__ h, float* __restrict__ out, int P)
{
    int p    = (blockIdx.x * blockDim.x + threadIdx.x) >> 5;
    int lane = threadIdx.x & 31;
    if (p >= P) return;
    int beg = g_offsets[p], end = g_offsets[p + 1];
    float4 m = make_float4(0.f, 0.f, 0.f, 0.f);
    for (int i = beg; i < end; i++) {
        float4 v = *(const float4*)(h + (size_t)i * HDIM + lane * 4);
        m.x = fmaxf(m.x, v.x); m.y = fmaxf(m.y, v.y);
        m.z = fmaxf(m.z, v.z); m.w = fmaxf(m.w, v.w);
    }
    *(float4*)(out + (size_t)p * HDIM + lane * 4) = m;
}

// ---------------- tf32 mma.sync helpers ----------------
__device__ __forceinline__ void cp_async16(float* s, const float* g) {
    unsigned sa = (unsigned)__cvta_generic_to_shared(s);
    asm volatile("cp.async.cg.shared.global [%0], [%1], 16;\n" :: "r"(sa), "l"(g));
}
__device__ __forceinline__ void cp_commit() {
    asm volatile("cp.async.commit_group;\n" ::: "memory");
}
template<int n> __device__ __forceinline__ void cp_wait() {
    asm volatile("cp.async.wait_group %0;\n" :: "n"(n) : "memory");
}
__device__ __forceinline__ void mma_tf32(float acc[4], const unsigned a[4], const unsigned b[2]) {
    asm volatile(
        "mma.sync.aligned.m16n8k8.row.col.f32.tf32.tf32.f32 "
        "{%0,%1,%2,%3},{%4,%5,%6,%7},{%8,%9},{%0,%1,%2,%3};\n"
        : "+f"(acc[0]), "+f"(acc[1]), "+f"(acc[2]), "+f"(acc[3])
        : "r"(a[0]), "r"(a[1]), "r"(a[2]), "r"(a[3]), "r"(b[0]), "r"(b[1]));
}

#define AS_STRIDE 36
#define WS_STRIDE 136
#define AS_BUF (128 * AS_STRIDE)
#define WS_BUF (32 * WS_STRIDE)
#define ENC_SMEM_FLOATS (2*AS_BUF + 2*WS_BUF + 512 + 128)
#define ENC_SMEM_BYTES (ENC_SMEM_FLOATS * 4)

// ---------------- aggw kernel: aggW = bias + agg @ W_bot  (P x 128, K=128) ---
__global__ __launch_bounds__(256, 2) void aggw_kernel(
    const float* __restrict__ agg, const float* __restrict__ Wb,
    const float* __restrict__ b, float* __restrict__ aggw, int P)
{
    extern __shared__ float sm[];
    float* As  = sm;
    float* Wsm = sm + 2 * AS_BUF;

    const int tid = threadIdx.x;
    const int lane = tid & 31;
    const int quad_r = lane >> 2, quad_c = lane & 3;
    const int warp = tid >> 5;
    const int warp_m = warp >> 1, warp_n = warp & 1;
    const int row0 = blockIdx.x * 128;

    float acc[2][8][4];
#pragma unroll
    for (int nt = 0; nt < 8; nt++) {
        float2 bv = *(const float2*)&b[warp_n * 64 + nt * 8 + quad_c * 2];
#pragma unroll
        for (int mf = 0; mf < 2; mf++) {
            acc[mf][nt][0] = bv.x; acc[mf][nt][1] = bv.y;
            acc[mf][nt][2] = bv.x; acc[mf][nt][3] = bv.y;
        }
    }

    auto issue_chunk = [&](int kc, int buf) {
        float* Ab = As + buf * AS_BUF;
        float* Wc = Wsm + buf * WS_BUF;
#pragma unroll
        for (int i = 0; i < 4; i++) {
            int idx = tid + i * 256;
            int r = idx >> 3, f = idx & 7;
            int gr = row0 + r; if (gr >= P) gr = P - 1;
            cp_async16(Ab + r * AS_STRIDE + f * 4,
                       agg + (size_t)gr * HDIM + kc * 32 + f * 4);
        }
#pragma unroll
        for (int i = 0; i < 4; i++) {
            int idx = tid + i * 256;
            int k = idx >> 5, f = idx & 31;
            cp_async16(Wc + k * WS_STRIDE + f * 4,
                       Wb + (size_t)(kc * 32 + k) * HDIM + f * 4);
        }
        cp_commit();
    };

    issue_chunk(0, 0);

#pragma unroll 1
    for (int kc = 0; kc < 4; kc++) {
        if (kc < 3) { issue_chunk(kc + 1, (kc + 1) & 1); cp_wait<1>(); }
        else        { cp_wait<0>(); }
        __syncthreads();
        const float* Ab = As + (kc & 1) * AS_BUF;
        const float* Wc = Wsm + (kc & 1) * WS_BUF;
#pragma unroll
        for (int ks = 0; ks < 4; ks++) {
            const int kk = ks * 8;
            unsigned afr[2][4];
#pragma unroll
            for (int mf = 0; mf < 2; mf++) {
                const float* p = Ab + (warp_m * 32 + mf * 16 + quad_r) * AS_STRIDE
                                    + kk + quad_c;
                afr[mf][0] = __float_as_uint(p[0]);
                afr[mf][1] = __float_as_uint(p[8 * AS_STRIDE]);
                afr[mf][2] = __float_as_uint(p[4]);
                afr[mf][3] = __float_as_uint(p[8 * AS_STRIDE + 4]);
            }
            unsigned bfr[8][2];
#pragma unroll
            for (int nt = 0; nt < 8; nt++) {
                const float* p = Wc + (kk + quad_c) * WS_STRIDE
                                    + warp_n * 64 + nt * 8 + quad_r;
                bfr[nt][0] = __float_as_uint(p[0]);
                bfr[nt][1] = __float_as_uint(p[4 * WS_STRIDE]);
            }
#pragma unroll
            for (int mf = 0; mf < 2; mf++)
#pragma unroll
                for (int nt = 0; nt < 8; nt++)
                    mma_tf32(acc[mf][nt], afr[mf], bfr[nt]);
        }
        __syncthreads();
    }

#pragma unroll
    for (int nt = 0; nt < 8; nt++) {
        int col = warp_n * 64 + nt * 8 + quad_c * 2;
#pragma unroll
        for (int mf = 0; mf < 2; mf++)
#pragma unroll
            for (int h = 0; h < 2; h++) {
                int grow = row0 + warp_m * 32 + mf * 16 + h * 8 + quad_r;
                if (grow < P)
                    *(float2*)(aggw + (size_t)grow * HDIM + col) =
                        make_float2(acc[mf][nt][2 * h], acc[mf][nt][2 * h + 1]);
            }
    }
}

// ---------------- encoder 1/2: z = h @ W_top + aggW[id]; LN; ReLU ------------
__global__ __launch_bounds__(256, 2) void enc_kernel(
    const float* __restrict__ hprev, const float* __restrict__ aggw,
    const float* __restrict__ Wt, const float* __restrict__ gw,
    const float* __restrict__ be, float* __restrict__ out, int N)
{
    extern __shared__ float sm[];
    float* As   = sm;
    float* Wsm  = sm + 2 * AS_BUF;
    float2* red2 = (float2*)(sm + 2*AS_BUF + 2*WS_BUF);
    int*   sidp = (int*)(sm + 2*AS_BUF + 2*WS_BUF + 512);

    const int tid = threadIdx.x;
    const int lane = tid & 31;
    const int quad_r = lane >> 2, quad_c = lane & 3;
    const int warp = tid >> 5;
    const int warp_m = warp >> 1, warp_n = warp & 1;
    const int row0 = blockIdx.x * 128;

    if (tid < 128) {
        int r = row0 + tid;
        sidp[tid] = g_sid[(r < N) ? r : (N - 1)];
    }
    __syncthreads();

    auto issue_chunk = [&](int kc, int buf) {
        float* Ab = As + buf * AS_BUF;
        float* Wc = Wsm + buf * WS_BUF;
#pragma unroll
        for (int i = 0; i < 4; i++) {
            int idx = tid + i * 256;
            int r = idx >> 3, f = idx & 7;
            int gr = row0 + r; if (gr >= N) gr = N - 1;
            cp_async16(Ab + r * AS_STRIDE + f * 4,
                       hprev + (size_t)gr * HDIM + kc * 32 + f * 4);
        }
#pragma unroll
        for (int i = 0; i < 4; i++) {
            int idx = tid + i * 256;
            int k = idx >> 5, f = idx & 31;
            cp_async16(Wc + k * WS_STRIDE + f * 4,
                       Wt + (size_t)(kc * 32 + k) * HDIM + f * 4);
        }
        cp_commit();
    };

    issue_chunk(0, 0);

    // accumulator init = aggW[id] gather (L2-resident table; overlaps chunk 0)
    float acc[2][8][4];
#pragma unroll
    for (int mf = 0; mf < 2; mf++)
#pragma unroll
        for (int h = 0; h < 2; h++) {
            int rl = warp_m * 32 + mf * 16 + h * 8 + quad_r;
            const float* base = aggw + (size_t)sidp[rl] * HDIM;
#pragma unroll
            for (int nt = 0; nt < 8; nt++) {
                float2 v = *(const float2*)(base + warp_n * 64 + nt * 8 + quad_c * 2);
                acc[mf][nt][2 * h]     = v.x;
                acc[mf][nt][2 * h + 1] = v.y;
            }
        }

#pragma unroll 1
    for (int kc = 0; kc < 4; kc++) {
        if (kc < 3) { issue_chunk(kc + 1, (kc + 1) & 1); cp_wait<1>(); }
        else        { cp_wait<0>(); }
        __syncthreads();

        const float* Ab = As + (kc & 1) * AS_BUF;
        const float* Wc = Wsm + (kc & 1) * WS_BUF;
#pragma unroll
        for (int ks = 0; ks < 4; ks++) {
            const int kk = ks * 8;
            unsigned afr[2][4];
#pragma unroll
            for (int mf = 0; mf < 2; mf++) {
                const float* p = Ab + (warp_m * 32 + mf * 16 + quad_r) * AS_STRIDE
                                    + kk + quad_c;
                afr[mf][0] = __float_as_uint(p[0]);
                afr[mf][1] = __float_as_uint(p[8 * AS_STRIDE]);
                afr[mf][2] = __float_as_uint(p[4]);
                afr[mf][3] = __float_as_uint(p[8 * AS_STRIDE + 4]);
            }
            unsigned bfr[8][2];
#pragma unroll
            for (int nt = 0; nt < 8; nt++) {
                const float* p = Wc + (kk + quad_c) * WS_STRIDE
                                    + warp_n * 64 + nt * 8 + quad_r;
                bfr[nt][0] = __float_as_uint(p[0]);
                bfr[nt][1] = __float_as_uint(p[4 * WS_STRIDE]);
            }
#pragma unroll
            for (int mf = 0; mf < 2; mf++)
#pragma unroll
                for (int nt = 0; nt < 8; nt++)
                    mma_tf32(acc[mf][nt], afr[mf], bfr[nt]);
        }
        __syncthreads();
    }

    // ---- epilogue: LayerNorm + ReLU (bias already inside aggW) ----
    float s[2][2], q[2][2];
#pragma unroll
    for (int mf = 0; mf < 2; mf++)
#pragma unroll
        for (int h = 0; h < 2; h++) {
            float ss = 0.f, qq = 0.f;
#pragma unroll
            for (int nt = 0; nt < 8; nt++) {
                float z0 = acc[mf][nt][2 * h], z1 = acc[mf][nt][2 * h + 1];
                ss += z0 + z1;
                qq += z0 * z0 + z1 * z1;
            }
            s[mf][h] = ss; q[mf][h] = qq;
        }
#pragma unroll
    for (int mk = 1; mk <= 2; mk <<= 1)
#pragma unroll
        for (int mf = 0; mf < 2; mf++)
#pragma unroll
            for (int h = 0; h < 2; h++) {
                s[mf][h] += __shfl_xor_sync(0xffffffffu, s[mf][h], mk);
                q[mf][h] += __shfl_xor_sync(0xffffffffu, q[mf][h], mk);
            }
    if (quad_c == 0) {
#pragma unroll
        for (int mf = 0; mf < 2; mf++)
#pragma unroll
            for (int h = 0; h < 2; h++) {
                int rl = warp_m * 32 + mf * 16 + h * 8 + quad_r;
                red2[rl * 2 + warp_n] = make_float2(s[mf][h], q[mf][h]);
            }
    }
    __syncthreads();
    float mu[2][2], rs[2][2];
#pragma unroll
    for (int mf = 0; mf < 2; mf++)
#pragma unroll
        for (int h = 0; h < 2; h++) {
            int rl = warp_m * 32 + mf * 16 + h * 8 + quad_r;
            float2 r0 = red2[rl * 2 + 0], r1 = red2[rl * 2 + 1];
            float ss = r0.x + r1.x, qq = r0.y + r1.y;
            float m = ss * (1.f / HDIM);
            float var = fmaf(qq, 1.f / HDIM, -m * m);
            mu[mf][h] = m;
            rs[mf][h] = rsqrtf(var + LN_EPS);
        }
#pragma unroll
    for (int nt = 0; nt < 8; nt++) {
        int col = warp_n * 64 + nt * 8 + quad_c * 2;
        float2 gv = *(const float2*)&gw[col];
        float2 ev = *(const float2*)&be[col];
#pragma unroll
        for (int mf = 0; mf < 2; mf++)
#pragma unroll
            for (int h = 0; h < 2; h++) {
                int grow = row0 + warp_m * 32 + mf * 16 + h * 8 + quad_r;
                if (grow < N) {
                    float z0 = acc[mf][nt][2 * h], z1 = acc[mf][nt][2 * h + 1];
                    float2 o;
                    o.x = fmaxf(fmaf((z0 - mu[mf][h]) * rs[mf][h], gv.x, ev.x), 0.f);
                    o.y = fmaxf(fmaf((z1 - mu[mf][h]) * rs[mf][h], gv.y, ev.y), 0.f);
                    *(float2*)(out + (size_t)grow * HDIM + col) = o;
                }
            }
    }
}

// ---------------- output tail ----------------
__global__ void tail_kernel(float* out, int tail) {
    int i = blockIdx.x * blockDim.x + threadIdx.x;
    float* base = out + (size_t)PNUM * HDIM;
    if (tail == PNUM) {
        if (i < PNUM) base[i] = (float)i;
    } else if (tail == 2 * PNUM) {
        if (i < PNUM) ((long long*)base)[i] = (long long)i;
    } else {
        if (i < tail) base[i] = (float)i;
    }
}

// ---------------- launch ----------------
extern "C" void kernel_launch(void* const* d_in, const int* in_sizes, int n_in,
                              void* d_out, int out_size) {
    const float* x   = (const float*)d_in[0];
    const void*  ids = d_in[1];
    const float* W0  = (const float*)d_in[2];
    const float* b0  = (const float*)d_in[3];
    const float* g0  = (const float*)d_in[4];
    const float* be0 = (const float*)d_in[5];
    const float* W1  = (const float*)d_in[6];
    const float* b1  = (const float*)d_in[7];
    const float* g1  = (const float*)d_in[8];
    const float* be1 = (const float*)d_in[9];
    const float* W2  = (const float*)d_in[10];
    const float* b2  = (const float*)d_in[11];
    const float* g2  = (const float*)d_in[12];
    const float* be2 = (const float*)d_in[13];

    const int N = in_sizes[0] / 9;
    const int P = PNUM;
    float* out = (float*)d_out;

    float *h0, *h1, *agg, *aggw;
    int* counts;
    cudaGetSymbolAddress((void**)&h0,   g_h0);
    cudaGetSymbolAddress((void**)&h1,   g_h1);
    cudaGetSymbolAddress((void**)&agg,  g_agg);
    cudaGetSymbolAddress((void**)&aggw, g_aggw);
    cudaGetSymbolAddress((void**)&counts, g_counts);

    cudaFuncSetAttribute(enc_kernel,
        cudaFuncAttributeMaxDynamicSharedMemorySize, ENC_SMEM_BYTES);
    cudaFuncSetAttribute(aggw_kernel,
        cudaFuncAttributeMaxDynamicSharedMemorySize, ENC_SMEM_BYTES);

    // 1) id normalization + CSR build (sorted order)
    detect_ids_kernel<<<1, 1>>>(ids);
    cudaMemsetAsync(counts, 0, (size_t)P * sizeof(int));
    prep_kernel<<<(N + 255) / 256, 256>>>(ids, N);
    scan_kernel<<<1, 1024>>>();
    scatter_kernel<<<(N + 255) / 256, 256>>>(N);

    // 2) enc0 -> h0 (sorted space)
    enc0_kernel<<<(N + 7) / 8, 256>>>(x, W0, b0, g0, be0, h0, N);

    // 3) layer 1: seg_max -> agg; aggW = b1 + agg@W1_bot; enc -> h1
    segmax_kernel<<<(P + 7) / 8, 256>>>(h0, agg, P);
    aggw_kernel<<<(P + 127) / 128, 256, ENC_SMEM_BYTES>>>(
        agg, W1 + (size_t)HDIM * HDIM, b1, aggw, P);
    enc_kernel<<<(N + 127) / 128, 256, ENC_SMEM_BYTES>>>(
        h0, aggw, W1, g1, be1, h1, N);

    // 4) layer 2
    segmax_kernel<<<(P + 7) / 8, 256>>>(h1, agg, P);
    aggw_kernel<<<(P + 127) / 128, 256, ENC_SMEM_BYTES>>>(
        agg, W2 + (size_t)HDIM * HDIM, b2, aggw, P);
    enc_kernel<<<(N + 127) / 128, 256, ENC_SMEM_BYTES>>>(
        h1, aggw, W2, g2, be2, h0, N);

    // 5) final seg_max -> d_out; arange tail
    segmax_kernel<<<(P + 7) / 8, 256>>>(h0, out, P);
    int tail = out_size - P * HDIM;
    if (tail > 0) {
        int elems = (tail == 2 * PNUM) ? PNUM : tail;
        tail_kernel<<<(elems + 255) / 256, 256>>>(out, tail);
    }
}